// round 1
// baseline (speedup 1.0000x reference)
#include <cuda_runtime.h>
#include <cstdint>

#define S_SUBJ   4
#define B_BATCH  64
#define K_VOX    40000
#define OUT_DIMN 768
#define V_VOX    (64*64*48)

#define OT      128          // outputs per block tile
#define MT      32           // samples per block tile
#define KSPLIT  25           // K split factor
#define KCHUNK  1600         // 40000 / 25
#define KC      32           // smem K chunk
#define NITER   (KCHUNK/KC)  // 50

// -------- device scratch (allocation-free per harness rules) --------
__device__ float g_G[(size_t)B_BATCH * K_VOX];   // gathered voxels, [slot][k]
__device__ int   g_subj[B_BATCH];                // subject per original sample
__device__ int   g_order[B_BATCH];               // slot -> original sample index
__device__ int   g_slotsubj[B_BATCH];            // slot -> subject
__device__ int   g_off[S_SUBJ + 1];              // subject -> slot range

// -------- 1) grouping + dtype detection --------
__global__ void setup_kernel(const void* idp) {
    if (threadIdx.x != 0) return;
    const int* w = (const int*)idp;
    // If id_batch is int64 (little-endian, values < 4), the high word of every
    // value is 0. Check odd words 1..63 (stays inside 256 bytes, valid for both
    // int32 and int64 buffers). For int32 data these are real ids (all-zero with
    // probability 4^-32).
    bool is64 = true;
    for (int i = 1; i < B_BATCH; i += 2) {
        if (w[i] != 0) { is64 = false; break; }
    }
    int subj[B_BATCH];
    for (int b = 0; b < B_BATCH; b++) {
        int s = is64 ? w[2 * b] : w[b];
        subj[b] = s;
        g_subj[b] = s;
    }
    int cnt[S_SUBJ];
    for (int s = 0; s < S_SUBJ; s++) cnt[s] = 0;
    for (int b = 0; b < B_BATCH; b++) cnt[subj[b]]++;
    int off = 0, pos[S_SUBJ];
    for (int s = 0; s < S_SUBJ; s++) { g_off[s] = off; pos[s] = off; off += cnt[s]; }
    g_off[S_SUBJ] = off;
    for (int b = 0; b < B_BATCH; b++) {
        int s = subj[b];
        int p = pos[s]++;
        g_order[p] = b;
        g_slotsubj[p] = s;
    }
}

// -------- 2) out = bias[subj[b]] (also un-poisons d_out) --------
__global__ void init_out_kernel(float* out, const float* bias) {
    int i = blockIdx.x * blockDim.x + threadIdx.x;
    if (i >= B_BATCH * OUT_DIMN) return;
    int b = i / OUT_DIMN;
    int o = i - b * OUT_DIMN;
    out[i] = bias[g_subj[b] * OUT_DIMN + o];
}

// -------- 3) gather: G[slot][k] = fmri[order[slot]][idx[subj][k]] --------
__global__ void gather_kernel(const float* __restrict__ fmri, const int* __restrict__ idx) {
    int slot = blockIdx.y;
    int k = blockIdx.x * blockDim.x + threadIdx.x;
    if (k >= K_VOX) return;
    int b = g_order[slot];
    int s = g_slotsubj[slot];
    g_G[(size_t)slot * K_VOX + k] = fmri[(size_t)b * V_VOX + idx[s * K_VOX + k]];
}

// -------- packed fp32x2 FMA (Blackwell-only PTX) --------
__device__ __forceinline__ unsigned long long fma2(unsigned long long a,
                                                   unsigned long long b,
                                                   unsigned long long c) {
    unsigned long long d;
    asm("fma.rn.f32x2 %0, %1, %2, %3;" : "=l"(d) : "l"(a), "l"(b), "l"(c));
    return d;
}

// -------- 4) grouped GEMM: out[b][o] += G[slot] . Wt[s][o] --------
__global__ void __launch_bounds__(256) gemm_kernel(const float* __restrict__ Wt,
                                                   float* __restrict__ out) {
    __shared__ __align__(16) float ws[OT * KC];  // [o][32], xor-swizzled in k
    __shared__ __align__(16) float gs[MT * KC];  // [m][32], xor-swizzled in k

    int tid = threadIdx.x;
    int s = blockIdx.y >> 1;
    int mtile = (blockIdx.y & 1) * MT;
    int off = g_off[s];
    int count = g_off[s + 1] - off;
    if (mtile >= count) return;
    int otile = blockIdx.x * OT;
    size_t k0 = (size_t)blockIdx.z * KCHUNK;

    // ---- global->smem load mappings ----
    int wo = tid >> 1;                 // 0..127 : weight row within tile
    int wk = (tid & 1) * 16;           // half-row of 32 floats
    const float* wgp = Wt + ((size_t)(s * OUT_DIMN + otile + wo)) * K_VOX + k0 + wk;
    int wsw = (wo & 7) << 2;
    float* wsp = ws + wo * KC;

    int gm = tid >> 3;                 // 0..31 : sample row within tile
    int gk = (tid & 7) * 4;
    int mglob = mtile + gm;
    int slot = off + (mglob < count ? mglob : count - 1);  // clamp (padded rows)
    const float* ggp = g_G + (size_t)slot * K_VOX + k0 + gk;
    int gsw = (gm & 7) << 2;
    float* gsp = gs + gm * KC;

    // ---- compute mapping: warp = 32 outputs (og), mg = sample group ----
    int og = tid & 31;
    int mg = tid >> 5;                 // 0..7
    int swW = (og & 7) << 2;

    unsigned long long acc[4][4];
#pragma unroll
    for (int i = 0; i < 4; i++)
#pragma unroll
        for (int r = 0; r < 4; r++) acc[i][r] = 0ULL;

    // register double-buffer for global loads
    float4 wpre[4];
    float4 gpre;
#pragma unroll
    for (int q = 0; q < 4; q++) wpre[q] = *(const float4*)(wgp + q * 4);
    gpre = *(const float4*)ggp;

    for (int it = 0; it < NITER; it++) {
        __syncthreads();
#pragma unroll
        for (int q = 0; q < 4; q++) {
            int kl = wk + q * 4;
            *(float4*)&wsp[kl ^ wsw] = wpre[q];
        }
        *(float4*)&gsp[gk ^ gsw] = gpre;
        __syncthreads();
        if (it + 1 < NITER) {
            const float* wn = wgp + (size_t)(it + 1) * KC;
#pragma unroll
            for (int q = 0; q < 4; q++) wpre[q] = *(const float4*)(wn + q * 4);
            gpre = *(const float4*)(ggp + (size_t)(it + 1) * KC);
        }
        // compute this chunk: 4 samples x 4 outputs per thread, f32x2 packed over k
#pragma unroll
        for (int kg = 0; kg < 8; kg++) {
            int kb = kg * 4;
            ulonglong2 wv[4];
#pragma unroll
            for (int r = 0; r < 4; r++)
                wv[r] = *(const ulonglong2*)&ws[(og + 32 * r) * KC + (kb ^ swW)];
#pragma unroll
            for (int i = 0; i < 4; i++) {
                int m = mg * 4 + i;
                ulonglong2 gv = *(const ulonglong2*)&gs[m * KC + (kb ^ ((m & 7) << 2))];
#pragma unroll
                for (int r = 0; r < 4; r++) {
                    acc[i][r] = fma2(gv.x, wv[r].x, acc[i][r]);
                    acc[i][r] = fma2(gv.y, wv[r].y, acc[i][r]);
                }
            }
        }
    }

    // epilogue: fold f32x2 halves, accumulate across K-splits
#pragma unroll
    for (int i = 0; i < 4; i++) {
        int m = mtile + mg * 4 + i;
        if (m >= count) continue;
        int b = g_order[off + m];
#pragma unroll
        for (int r = 0; r < 4; r++) {
            unsigned long long a = acc[i][r];
            float lo = __uint_as_float((unsigned)(a & 0xffffffffULL));
            float hi = __uint_as_float((unsigned)(a >> 32));
            int o = otile + og + 32 * r;
            atomicAdd(&out[b * OUT_DIMN + o], lo + hi);
        }
    }
}

extern "C" void kernel_launch(void* const* d_in, const int* in_sizes, int n_in,
                              void* d_out, int out_size) {
    (void)in_sizes; (void)n_in; (void)out_size;
    const void*  idp  = d_in[0];                 // id_batch (int64 or int32)
    const float* fmri = (const float*)d_in[1];   // [B, D, H, W]
    const int*   idx  = (const int*)d_in[2];     // [S, K]
    const float* Wt   = (const float*)d_in[3];   // [S, OUT, K]
    const float* bias = (const float*)d_in[4];   // [S, OUT]
    float* out = (float*)d_out;                  // [B, 1, OUT]

    setup_kernel<<<1, 32>>>(idp);
    init_out_kernel<<<(B_BATCH * OUT_DIMN + 255) / 256, 256>>>(out, bias);
    gather_kernel<<<dim3((K_VOX + 255) / 256, B_BATCH), 256>>>(fmri, idx);
    gemm_kernel<<<dim3(OUT_DIMN / OT, 8, KSPLIT), 256>>>(Wt, out);
}